// round 9
// baseline (speedup 1.0000x reference)
#include <cuda_runtime.h>

#define Hdim 128
#define PREP_BLOCKS 32
#define MAIN_BLOCKS 148
#define MAIN_THREADS 512
#define WARPS_PB (MAIN_THREADS / 32)

// scratch (no allocations allowed)
__device__ float g_u_part[PREP_BLOCKS][Hdim];
__device__ float g_c_part[PREP_BLOCKS];
__device__ double g_sum;
__device__ unsigned long long g_maxkey;
__device__ unsigned g_count;

struct f8 { float a0,a1,a2,a3,a4,a5,a6,a7; };

// 256-bit feat load with L2 evict_last (harmless; legal encoding on sm_103a)
__device__ __forceinline__ f8 ldg_keep8(const float* __restrict__ p) {
    f8 v;
    asm("ld.global.nc.L2::evict_last.v8.b32 {%0,%1,%2,%3,%4,%5,%6,%7}, [%8];"
        : "=f"(v.a0), "=f"(v.a1), "=f"(v.a2), "=f"(v.a3),
          "=f"(v.a4), "=f"(v.a5), "=f"(v.a6), "=f"(v.a7)
        : "l"(p));
    return v;
}

__device__ __forceinline__ void loadrow(const float* __restrict__ feat, int node,
                                        int sub, f8& x0, f8& x1, f8& x2, f8& x3)
{
    const float* row = feat + (size_t)node * Hdim;
    x0 = ldg_keep8(row + (sub     ) * 8);
    x1 = ldg_keep8(row + (sub +  4) * 8);
    x2 = ldg_keep8(row + (sub +  8) * 8);
    x3 = ldg_keep8(row + (sub + 12) * 8);
}

__device__ __forceinline__ float dot32(const float* __restrict__ u,
                                       const f8& x0, const f8& x1,
                                       const f8& x2, const f8& x3)
{
    float e0, e1;
    e0 = u[0] * x0.a0;               e1 = u[1] * x0.a1;
    e0 = fmaf(u[2],  x0.a2, e0);     e1 = fmaf(u[3],  x0.a3, e1);
    e0 = fmaf(u[4],  x0.a4, e0);     e1 = fmaf(u[5],  x0.a5, e1);
    e0 = fmaf(u[6],  x0.a6, e0);     e1 = fmaf(u[7],  x0.a7, e1);
    e0 = fmaf(u[8],  x1.a0, e0);     e1 = fmaf(u[9],  x1.a1, e1);
    e0 = fmaf(u[10], x1.a2, e0);     e1 = fmaf(u[11], x1.a3, e1);
    e0 = fmaf(u[12], x1.a4, e0);     e1 = fmaf(u[13], x1.a5, e1);
    e0 = fmaf(u[14], x1.a6, e0);     e1 = fmaf(u[15], x1.a7, e1);
    e0 = fmaf(u[16], x2.a0, e0);     e1 = fmaf(u[17], x2.a1, e1);
    e0 = fmaf(u[18], x2.a2, e0);     e1 = fmaf(u[19], x2.a3, e1);
    e0 = fmaf(u[20], x2.a4, e0);     e1 = fmaf(u[21], x2.a5, e1);
    e0 = fmaf(u[22], x2.a6, e0);     e1 = fmaf(u[23], x2.a7, e1);
    e0 = fmaf(u[24], x3.a0, e0);     e1 = fmaf(u[25], x3.a1, e1);
    e0 = fmaf(u[26], x3.a2, e0);     e1 = fmaf(u[27], x3.a3, e1);
    e0 = fmaf(u[28], x3.a4, e0);     e1 = fmaf(u[29], x3.a5, e1);
    e0 = fmaf(u[30], x3.a6, e0);     e1 = fmaf(u[31], x3.a7, e1);
    return e0 + e1;
}

// ---------------------------------------------------------------------------
// K1 (prep): unchanged. 32 blocks x 128 threads.
// ---------------------------------------------------------------------------
__global__ void __launch_bounds__(128) k_prep(const float* __restrict__ feat,
                                              const float* __restrict__ W1,
                                              const float* __restrict__ b1,
                                              const float* __restrict__ W2,
                                              const float* __restrict__ b2,
                                              const int*   __restrict__ prev)
{
    __shared__ float sphi[16];

    const int lane = threadIdx.x & 31;
    const int warp = threadIdx.x >> 5;
    const int j0   = blockIdx.x * 16;
    const int p    = prev[0];

    const float4 x = ((const float4*)(feat + (size_t)p * Hdim))[lane];

#pragma unroll
    for (int jj = 0; jj < 4; jj++) {
        const int j = j0 + warp * 4 + jj;
        const float4 w = ((const float4*)(W1 + (size_t)j * Hdim))[lane];
        float d = fmaf(w.x, x.x, fmaf(w.y, x.y, fmaf(w.z, x.z, w.w * x.w)));
        d += __shfl_xor_sync(0xffffffffu, d, 16);
        d += __shfl_xor_sync(0xffffffffu, d, 8);
        d += __shfl_xor_sync(0xffffffffu, d, 4);
        d += __shfl_xor_sync(0xffffffffu, d, 2);
        d += __shfl_xor_sync(0xffffffffu, d, 1);
        if (lane == 0) sphi[warp * 4 + jj] = d + b1[j];
    }
    __syncthreads();

    const int h = threadIdx.x;
    float acc = 0.0f;
#pragma unroll
    for (int jj = 0; jj < 16; jj++) {
        acc = fmaf(sphi[jj], W2[(size_t)(j0 + jj) * Hdim + h], acc);
    }
    g_u_part[blockIdx.x][h] = acc;

    if (threadIdx.x == 0) {
        float cp = 0.0f;
#pragma unroll
        for (int jj = 0; jj < 16; jj++) cp = fmaf(sphi[jj], b2[j0 + jj], cp);
        g_c_part[blockIdx.x] = cp;
        if (blockIdx.x == 0) { g_sum = 0.0; g_maxkey = 0ull; g_count = 0u; }
    }
}

// ---------------------------------------------------------------------------
// K2 (main): persistent, exactly one wave (148 blocks x 512 threads).
// Each warp grid-strides over 32-node chunks with next-chunk adj prefetch
// and double-buffered row-load batches (8 rows x 512B per batch).
// ---------------------------------------------------------------------------
__global__ void __launch_bounds__(MAIN_THREADS, 1)
k_main(const float* __restrict__ feat,
       const float* __restrict__ adj,
       float* __restrict__ out,
       int N, int out_size)
{
    __shared__ float              su[Hdim];
    __shared__ float              sc;
    __shared__ float              ssum[WARPS_PB];
    __shared__ unsigned long long skey[WARPS_PB];

    const int lane  = threadIdx.x & 31;
    const int wwarp = threadIdx.x >> 5;
    const int gwarp = blockIdx.x * WARPS_PB + wwarp;
    const int nwarp = gridDim.x * WARPS_PB;

    // issue first adj prefetch BEFORE the su-reconstruction loads
    int  c    = gwarp;
    int  base = c * 32;
    float a_cur = 0.0f;
    if (base + lane < N) a_cur = __ldg(adj + base + lane);

    // Reconstruct u (overlaps with the adj load above)
    if (threadIdx.x < Hdim) {
        float a = 0.0f;
#pragma unroll
        for (int pb = 0; pb < PREP_BLOCKS; pb++) a += g_u_part[pb][threadIdx.x];
        su[threadIdx.x] = a;
    }
    if (threadIdx.x == Hdim) {
        float a = 0.0f;
#pragma unroll
        for (int pb = 0; pb < PREP_BLOCKS; pb++) a += g_c_part[pb];
        sc = a;
    }
    __syncthreads();

    const int sub = lane & 3;    // 8-float slot within row (0..3)
    const int grp = lane >> 2;   // which of 8 concurrent rows (0..7)

    float ureg[32];
#pragma unroll
    for (int t = 0; t < 4; t++)
#pragma unroll
        for (int q = 0; q < 8; q++)
            ureg[t * 8 + q] = su[(sub + 4 * t) * 8 + q];
    const float cc = sc;

    float lsum = 0.0f;
    unsigned long long lkey = 0ull;

    while (base < N) {
        // prefetch next chunk's adj immediately
        const int cn    = c + nwarp;
        const int basen = cn * 32;
        float a_next = 0.0f;
        if (basen < N && basen + lane < N) a_next = __ldg(adj + basen + lane);

        const unsigned mask = __ballot_sync(0xffffffffu, a_cur != 0.0f);
        const int m      = __popc(mask);
        const int nvalid = (N - base >= 32) ? 32 : (N - base);
        if (lane == 0) lsum += (float)(nvalid - m);   // exp(0) per masked node

        // double-buffered batches of 8 rows
        int rA = (int)__fns(mask, 0, grp + 1);
        f8 xA0, xA1, xA2, xA3;
        if (rA >= 0) loadrow(feat, base + rA, sub, xA0, xA1, xA2, xA3);

        for (int j = 0; j < m; j += 8) {
            const int rB = (int)__fns(mask, 0, j + 8 + grp + 1);
            f8 xB0, xB1, xB2, xB3;
            if (rB >= 0) loadrow(feat, base + rB, sub, xB0, xB1, xB2, xB3);

            float d = (rA >= 0) ? dot32(ureg, xA0, xA1, xA2, xA3) : 0.0f;
            d += __shfl_xor_sync(0xffffffffu, d, 2);
            d += __shfl_xor_sync(0xffffffffu, d, 1);

            if (sub == 0 && rA >= 0) {
                const float s    = (d + cc) * 0.04419417382415922f; // 1/sqrt(512)
                const float attn = 10.0f * tanhf(s);
                lsum += expf(attn);
                if (attn != 0.0f) {
                    const unsigned n   = (unsigned)(base + rA);
                    const unsigned b   = __float_as_uint(attn);
                    const unsigned enc = (b & 0x80000000u) ? ~b : (b | 0x80000000u);
                    const unsigned long long key =
                        ((unsigned long long)enc << 32) |
                        (unsigned long long)(0xFFFFFFFFu - n);
                    if (key > lkey) lkey = key;
                }
            }
            rA  = rB;
            xA0 = xB0; xA1 = xB1; xA2 = xB2; xA3 = xB3;
        }

        a_cur = a_next;
        c     = cn;
        base  = basen;
    }

    // warp-level reduce of lsum / lkey
#pragma unroll
    for (int s = 16; s; s >>= 1) {
        lsum += __shfl_xor_sync(0xffffffffu, lsum, s);
        const unsigned long long o = __shfl_xor_sync(0xffffffffu, lkey, s);
        if (o > lkey) lkey = o;
    }

    if (lane == 0) { ssum[wwarp] = lsum; skey[wwarp] = lkey; }
    __syncthreads();

    if (threadIdx.x == 0) {
        float bs = 0.0f;
        unsigned long long bk = 0ull;
#pragma unroll
        for (int i = 0; i < WARPS_PB; i++) {
            bs += ssum[i];
            if (skey[i] > bk) bk = skey[i];
        }
        atomicAdd(&g_sum, (double)bs);
        atomicMax(&g_maxkey, bk);
        __threadfence();
        const unsigned done = atomicAdd(&g_count, 1u);
        if (done == gridDim.x - 1u) {
            const double total = atomicAdd(&g_sum, 0.0);
            const unsigned long long k = atomicMax(&g_maxkey, 0ull);
            float pidx = 0.0f, pval = 0.0f;
            if (k != 0ull) {
                const unsigned enc = (unsigned)(k >> 32);
                const unsigned bb  = (enc & 0x80000000u) ? (enc ^ 0x80000000u) : ~enc;
                const float amax   = __uint_as_float(bb);
                const int   idx    = (int)(0xFFFFFFFFu - (unsigned)(k & 0xFFFFFFFFull));
                pidx = (float)idx;
                pval = (float)(exp((double)amax) / total);
            }
            out[0] = pidx;
            if (out_size > 1) out[1] = pval;
        }
    }
}

// ---------------------------------------------------------------------------
// inputs (metadata order): output[N,128], adj[N], W1[512,128], b1[512],
//                          W2[512,128], b2[512], prev_node (int scalar)
// ---------------------------------------------------------------------------
extern "C" void kernel_launch(void* const* d_in, const int* in_sizes, int n_in,
                              void* d_out, int out_size)
{
    const float* feat = (const float*)d_in[0];
    const float* adj  = (const float*)d_in[1];
    const float* W1   = (const float*)d_in[2];
    const float* b1   = (const float*)d_in[3];
    const float* W2   = (const float*)d_in[4];
    const float* b2   = (const float*)d_in[5];
    const int*   prev = (const int*)d_in[6];
    float* out = (float*)d_out;

    const int N = in_sizes[1];   // adj has N elements

    k_prep<<<PREP_BLOCKS, 128>>>(feat, W1, b1, W2, b2, prev);
    k_main<<<MAIN_BLOCKS, MAIN_THREADS>>>(feat, adj, out, N, out_size);
}